// round 14
// baseline (speedup 1.0000x reference)
#include <cuda_runtime.h>
#include <cstdint>

#define NC      32
#define NSTEPS  32
#define DDIM    30
#define BLOCK   256
#define PPT     8
#define MBINS   16384          // 2^14 bins per theta
#define NT_MAX  8

// Per-(theta,bin) composed affine; A==NaN => impure bin (slow path).
__device__ float2 g_tab[NT_MAX * MBINS];

// Build per-theta cell transforms into s0/s1 (threads 0..31).
__device__ __forceinline__ void build_table(const float* __restrict__ theta,
                                            const float* __restrict__ basis,
                                            int t, int tid,
                                            float* s0, float* s1)
{
    if (tid < NC) {
        const float dT = 1.0f / (float)NSTEPS;
        const float* __restrict__ ba = basis + (2 * tid)     * DDIM;
        const float* __restrict__ bb = basis + (2 * tid + 1) * DDIM;
        const float* __restrict__ th = theta + t * DDIM;
        float a = 0.0f, b = 0.0f;
        #pragma unroll
        for (int j = 0; j < DDIM; ++j) {
            float tj = th[j];
            a = fmaf(ba[j], tj, a);
            b = fmaf(bb[j], tj, b);
        }
        a *= dT;
        b *= dT;
        float ea  = expf(a);
        float phi = (fabsf(a) < 1e-6f) ? (1.0f + 0.5f * a) : (expm1f(a) / a);
        s0[tid] = ea;
        s1[tid] = b * phi;
    }
}

// Magic-number cell index: bits = 0x4B000000 + floor(x*32), exact (RZ fma).
// Low 5 bits == cell; __shfl_sync wraps srcLane mod 32.
__device__ __forceinline__ int cell_bits(float x)
{
    int b = (int)__float_as_uint(__fmaf_rz(x, 32.0f, 8388608.0f));
    b = max(b, 0x4B000000);
    b = min(b, 0x4B00001F);
    return b;
}

// ---------------------------------------------------------------------------
// Setup: one thread per (theta, bin); trace both bin edges with the SHFL
// table; purity = identical cell at every step; emit composed (A,B) or NaN.
// ---------------------------------------------------------------------------
__global__ __launch_bounds__(BLOCK)
void setup_kernel(const float* __restrict__ theta,
                  const float* __restrict__ basis)
{
    __shared__ float s0[NC], s1[NC];
    const int t   = blockIdx.y;
    const int tid = threadIdx.x;

    build_table(theta, basis, t, tid, s0, s1);
    __syncthreads();

    const float T0 = s0[tid & 31];
    const float T1 = s1[tid & 31];

    const int bin = blockIdx.x * BLOCK + tid;
    float xl = (float)bin       * (1.0f / (float)MBINS);  // exact fp32
    float xr = (float)(bin + 1) * (1.0f / (float)MBINS);

    float A = 1.0f, B = 0.0f;
    bool pure = true;

    #pragma unroll
    for (int s = 0; s < NSTEPS; ++s) {
        int bl = cell_bits(xl);
        int br = cell_bits(xr);
        pure = pure && (bl == br);
        float t0l = __shfl_sync(0xFFFFFFFFu, T0, bl);
        float t1l = __shfl_sync(0xFFFFFFFFu, T1, bl);
        float t0r = __shfl_sync(0xFFFFFFFFu, T0, br);
        float t1r = __shfl_sync(0xFFFFFFFFu, T1, br);
        xl = fmaf(t0l, xl, t1l);
        xr = fmaf(t0r, xr, t1r);
        A  = A * t0l;
        B  = fmaf(t0l, B, t1l);
    }

    g_tab[t * MBINS + bin] =
        pure ? make_float2(A, B)
             : make_float2(__int_as_float(0x7FC00000), 0.0f);
}

// ---------------------------------------------------------------------------
// Main: batched point loads -> batched independent table gathers -> fma+store;
// impure lanes (~6%) compacted and iterated with a UNIFORM-trip-count loop.
// ---------------------------------------------------------------------------
__global__ __launch_bounds__(BLOCK)
void main_kernel(const float* __restrict__ points,
                 const float* __restrict__ theta,
                 const float* __restrict__ basis,
                 float* __restrict__ out,
                 int n_points)
{
    __shared__ float s0[NC], s1[NC];
    __shared__ int   s_list[BLOCK * PPT];
    __shared__ int   s_cnt;

    const int t    = blockIdx.y;
    const int tid  = threadIdx.x;
    const int lane = tid & 31;

    if (tid == 0) s_cnt = 0;
    build_table(theta, basis, t, tid, s0, s1);
    __syncthreads();

    const float T0 = s0[lane];
    const float T1 = s1[lane];

    const float2* __restrict__ bt = g_tab + t * MBINS;
    float* __restrict__ o = out + (size_t)t * (size_t)n_points;

    // Contiguous per-thread tile of 8 points -> two LDG.128.
    const int base = blockIdx.x * (BLOCK * PPT) + tid * PPT;
    const bool full = (base + PPT <= n_points);

    float x[PPT];
    if (full) {
        const float4* p4 = (const float4*)(points + base);
        float4 a0 = __ldg(&p4[0]);
        float4 a1 = __ldg(&p4[1]);
        x[0] = a0.x; x[1] = a0.y; x[2] = a0.z; x[3] = a0.w;
        x[4] = a1.x; x[5] = a1.y; x[6] = a1.z; x[7] = a1.w;
    } else {
        #pragma unroll
        for (int k = 0; k < PPT; ++k) {
            int idx = base + k;
            x[k] = (idx < n_points) ? points[idx] : 0.5f;
        }
    }

    // All 8 bin indices (exact: multiply by 2^14 is exact), then all 8
    // gathers issued back-to-back (MLP = 8 per thread).
    int bin[PPT];
    bool oob[PPT];
    #pragma unroll
    for (int k = 0; k < PPT; ++k) {
        int v = (int)__fmul_rz(x[k], (float)MBINS);
        int c = min(max(v, 0), MBINS - 1);
        oob[k] = (v != c);
        bin[k] = c;
    }
    float2 ab[PPT];
    #pragma unroll
    for (int k = 0; k < PPT; ++k)
        ab[k] = __ldg(&bt[bin[k]]);

    // Consume: store fast result unconditionally (impure overwritten later).
    // Mask bits only for VALID indices so reserved slots == written slots.
    int mask = 0;
    #pragma unroll
    for (int k = 0; k < PPT; ++k) {
        int idx = base + k;
        bool bad = (ab[k].x != ab[k].x) || oob[k];
        if (idx < n_points) {
            o[idx] = fmaf(ab[k].x, x[k], ab[k].y);
            if (bad) mask |= 1 << k;
        }
    }

    // Warp-aggregated compaction of impure points.
    {
        int cnt = __popc((unsigned)mask);
        int scan = cnt;
        #pragma unroll
        for (int d = 1; d < 32; d <<= 1) {
            int v = __shfl_up_sync(0xFFFFFFFFu, scan, d);
            if (lane >= d) scan += v;
        }
        int wtot = __shfl_sync(0xFFFFFFFFu, scan, 31);
        int wbase = 0;
        if (wtot) {
            if (lane == 31) wbase = atomicAdd(&s_cnt, wtot);
            wbase = __shfl_sync(0xFFFFFFFFu, wbase, 31);
            int pos = wbase + scan - cnt;
            #pragma unroll
            for (int k = 0; k < PPT; ++k)
                if (mask & (1 << k)) s_list[pos++] = base + k;
        }
    }
    __syncthreads();

    // Slow path: exact reference iteration with the SHFL table.
    // UNIFORM trip count so every __shfl_sync has all 32 lanes present.
    const int n_imp  = s_cnt;
    const int n_iter = (n_imp + BLOCK - 1) / BLOCK;
    for (int j = 0; j < n_iter; ++j) {
        int  e   = j * BLOCK + tid;
        bool act = (e < n_imp);
        int  idx = act ? s_list[e] : 0;
        float xx = points[idx];               // idx 0 safe for inactive lanes
        #pragma unroll
        for (int s = 0; s < NSTEPS; ++s) {
            int bi = cell_bits(xx);
            float t0 = __shfl_sync(0xFFFFFFFFu, T0, bi);
            float t1 = __shfl_sync(0xFFFFFFFFu, T1, bi);
            xx = fmaf(t0, xx, t1);
        }
        if (act) o[idx] = xx;
    }
}

extern "C" void kernel_launch(void* const* d_in, const int* in_sizes, int n_in,
                              void* d_out, int out_size)
{
    const float* points = (const float*)d_in[0];  // [1, n_points]
    const float* theta  = (const float*)d_in[1];  // [n_theta, 30]
    const float* basis  = (const float*)d_in[2];  // [64, 30]
    float* out = (float*)d_out;                   // [n_theta, 1, n_points]

    const int n_points = in_sizes[0];
    const int n_theta  = in_sizes[1] / DDIM;

    dim3 sgrid(MBINS / BLOCK, n_theta);
    setup_kernel<<<sgrid, BLOCK>>>(theta, basis);

    dim3 mgrid((n_points + BLOCK * PPT - 1) / (BLOCK * PPT), n_theta);
    main_kernel<<<mgrid, BLOCK>>>(points, theta, basis, out, n_points);
}